// round 1
// baseline (speedup 1.0000x reference)
#include <cuda_runtime.h>
#include <math.h>

// Problem constants (fixed by setup_inputs)
#define DIM     256
#define BATCH   4
#define NODES   2048
#define MAXDEG  64
#define POOLMAX 1024   // max pooled n (after first pool)

// ---------------- persistent device scratch (no allocs allowed) --------------
__device__ float g_h [BATCH*NODES*DIM];
__device__ float g_hn[BATCH*NODES*DIM];
__device__ float g_t [BATCH*NODES*DIM];
__device__ float g_pe[NODES*DIM];
__device__ float g_score[BATCH*NODES];
__device__ float g_gate [BATCH*POOLMAX];
__device__ float g_ms[BATCH*2*DIM];
__device__ float g_posstat[8];   // mean[3], invstd[3]
__device__ float g_pnorm[4];     // 1/||pool_p[dep]||
__device__ int   g_idx[BATCH*POOLMAX];
__device__ int   g_map[BATCH*NODES];
__device__ int   g_cols0[NODES*MAXDEG];
__device__ int   g_cnt0 [NODES];
__device__ int   g_colsA[BATCH*POOLMAX*MAXDEG];
__device__ int   g_cntA [BATCH*POOLMAX];
__device__ int   g_colsB[BATCH*POOLMAX*MAXDEG];
__device__ int   g_cntB [BATCH*POOLMAX];

// ---------------------------- small utility kernels --------------------------

// mean / (std ddof=1 over B*N tiled rows) of pos columns
__global__ void pos_stats_kernel(const float* __restrict__ pos) {
    __shared__ float red[256];
    __shared__ float smean;
    int t = threadIdx.x;
    for (int c = 0; c < 3; c++) {
        float s = 0.f;
        for (int i = t; i < NODES; i += 256) s += pos[i*3 + c];
        red[t] = s; __syncthreads();
        for (int o = 128; o > 0; o >>= 1) { if (t < o) red[t] += red[t+o]; __syncthreads(); }
        if (t == 0) smean = red[0] / (float)NODES;
        __syncthreads();
        float m = smean;
        float ss = 0.f;
        for (int i = t; i < NODES; i += 256) { float d = pos[i*3 + c] - m; ss += d*d; }
        red[t] = ss; __syncthreads();
        for (int o = 128; o > 0; o >>= 1) { if (t < o) red[t] += red[t+o]; __syncthreads(); }
        if (t == 0) {
            float var = (float)BATCH * red[0] / (float)(BATCH*NODES - 1);
            g_posstat[c]   = m;
            g_posstat[3+c] = 1.f / (sqrtf(var) + 1e-8f);
        }
        __syncthreads();
    }
}

// inverse norms of the 3 pooling projection vectors
__global__ void pool_norms_kernel(const float* __restrict__ pp) {
    __shared__ float red[256];
    int t = threadIdx.x;
    for (int dep = 0; dep < 3; dep++) {
        float v = pp[dep*DIM + t];
        red[t] = v*v; __syncthreads();
        for (int o = 128; o > 0; o >>= 1) { if (t < o) red[t] += red[t+o]; __syncthreads(); }
        if (t == 0) g_pnorm[dep] = 1.f / sqrtf(red[0]);
        __syncthreads();
    }
}

// pe_mid = silu(pn @ pw1 + pb1)  -> g_hn  (only N distinct rows since pos is tiled)
__global__ void pos_mid_kernel(const float* __restrict__ pos,
                               const float* __restrict__ pw1,
                               const float* __restrict__ pb1) {
    int i = blockIdx.x, d = threadIdx.x;
    __shared__ float pn[3];
    if (d < 3) pn[d] = (pos[i*3 + d] - g_posstat[d]) * g_posstat[3+d];
    __syncthreads();
    float a = pb1[d] + pn[0]*pw1[d] + pn[1]*pw1[DIM + d] + pn[2]*pw1[2*DIM + d];
    g_hn[i*DIM + d] = a / (1.f + __expf(-a));
}

// h = x @ in_w + in_b + pe[row % N]
__global__ void embed_kernel(const float* __restrict__ x,
                             const float* __restrict__ in_w,
                             const float* __restrict__ in_b) {
    int r = blockIdx.x, d = threadIdx.x;
    __shared__ float xr[16];
    if (d < 16) xr[d] = x[r*16 + d];
    __syncthreads();
    float a = in_b[d] + g_pe[(r & (NODES-1))*DIM + d];
#pragma unroll
    for (int k = 0; k < 16; k++) a += xr[k]*in_w[k*DIM + d];
    g_h[(size_t)r*DIM + d] = a;
}

// adj -> CSR (level 0, shared across batches). one warp per row.
__global__ void build_csr_kernel(const float* __restrict__ adj) {
    int warp = (blockIdx.x*blockDim.x + threadIdx.x) >> 5;
    int lane = threadIdx.x & 31;
    if (warp >= NODES) return;
    int base = 0;
    for (int it = 0; it < NODES/32; it++) {
        int col = it*32 + lane;
        float v = adj[(size_t)warp*NODES + col];
        unsigned m = __ballot_sync(0xffffffffu, v > 0.f);
        if (v > 0.f) {
            int p = base + __popc(m & ((1u << lane) - 1u));
            if (p < MAXDEG) g_cols0[warp*MAXDEG + p] = col;
        }
        base += __popc(m);
    }
    if (lane == 0) g_cnt0[warp] = base < MAXDEG ? base : MAXDEG;
}

// layernorm (biased var) with per-block gamma/beta. one warp per row.
__global__ void ln_kernel(const float* __restrict__ H, float* __restrict__ HN,
                          const float* __restrict__ gam, const float* __restrict__ bet,
                          int rows) {
    int warp = (blockIdx.x*blockDim.x + threadIdx.x) >> 5;
    int lane = threadIdx.x & 31;
    if (warp >= rows) return;
    const float* hr = H + (size_t)warp*DIM;
    float v[8]; float s = 0.f;
#pragma unroll
    for (int q = 0; q < 8; q++) { v[q] = hr[lane + 32*q]; s += v[q]; }
#pragma unroll
    for (int o = 16; o; o >>= 1) s += __shfl_xor_sync(0xffffffffu, s, o);
    float m = s * (1.f/DIM);
    float vs = 0.f;
#pragma unroll
    for (int q = 0; q < 8; q++) { float d = v[q] - m; vs += d*d; }
#pragma unroll
    for (int o = 16; o; o >>= 1) vs += __shfl_xor_sync(0xffffffffu, vs, o);
    float rstd = rsqrtf(vs * (1.f/DIM) + 1e-5f);
#pragma unroll
    for (int q = 0; q < 8; q++) {
        int d = lane + 32*q;
        HN[(size_t)warp*DIM + d] = (v[q] - m)*rstd*gam[d] + bet[d];
    }
}

// t = (1+eps)*hn + sum_{j in N(i)} hn[j]   (sparse SpMM + combine)
__global__ void combine_kernel(int n, int adjSel, const float* __restrict__ beps, int blk) {
    int b = blockIdx.x / n, i = blockIdx.x % n, d = threadIdx.x;
    const int* cols; const int* cnt; int rowbase;
    if (adjSel == 0)      { cols = g_cols0; cnt = g_cnt0; rowbase = i; }
    else if (adjSel == 1) { cols = g_colsA; cnt = g_cntA; rowbase = b*POOLMAX + i; }
    else                  { cols = g_colsB; cnt = g_cntB; rowbase = b*POOLMAX + i; }
    __shared__ int cs[MAXDEG];
    int c = cnt[rowbase];
    if (d < c) cs[d] = cols[rowbase*MAXDEG + d];
    __syncthreads();
    float eps = beps[blk];
    const float* hb = g_hn + (size_t)b*n*DIM;
    float acc = (1.f + eps)*hb[(size_t)i*DIM + d];
    for (int q = 0; q < c; q++) acc += hb[(size_t)cs[q]*DIM + d];
    g_t[((size_t)b*n + i)*DIM + d] = acc;
}

// ------------------------------ SGEMM (M x 256 x 256) ------------------------
// 128x128 block tile, BK=8, 256 threads, 8x8 per thread.
// mode 0: C = acc + bias ; mode 1: C = silu(acc + bias) ; mode 2: C = res + acc + bias
__global__ void sgemm_kernel(const float* __restrict__ A, const float* __restrict__ Bw,
                             const float* __restrict__ bias, const float* __restrict__ res,
                             float* __restrict__ C, int M, int mode) {
    __shared__ float As[8][128];
    __shared__ float Bs[8][128];
    int t  = threadIdx.x;
    int bm = blockIdx.y, bn = blockIdx.x;
    int ty = t >> 4, tx = t & 15;
    int arow = t >> 1, acol4 = (t & 1)*4;
    int brow = t >> 5, bcol4 = (t & 31)*4;
    const float* Ab = A  + (size_t)bm*128*DIM;
    const float* Bb = Bw + bn*128;
    float acc[8][8];
#pragma unroll
    for (int i = 0; i < 8; i++)
#pragma unroll
        for (int j = 0; j < 8; j++) acc[i][j] = 0.f;

    for (int k0 = 0; k0 < DIM; k0 += 8) {
        float4 av = *(const float4*)(Ab + (size_t)arow*DIM + k0 + acol4);
        float4 bv = *(const float4*)(Bb + (size_t)(k0 + brow)*DIM + bcol4);
        __syncthreads();
        As[acol4 + 0][arow] = av.x;
        As[acol4 + 1][arow] = av.y;
        As[acol4 + 2][arow] = av.z;
        As[acol4 + 3][arow] = av.w;
        *(float4*)&Bs[brow][bcol4] = bv;
        __syncthreads();
#pragma unroll
        for (int kk = 0; kk < 8; kk++) {
            float a[8], bfr[8];
            *(float4*)&a[0]   = *(const float4*)&As[kk][ty*8];
            *(float4*)&a[4]   = *(const float4*)&As[kk][ty*8 + 4];
            *(float4*)&bfr[0] = *(const float4*)&Bs[kk][tx*8];
            *(float4*)&bfr[4] = *(const float4*)&Bs[kk][tx*8 + 4];
#pragma unroll
            for (int i = 0; i < 8; i++)
#pragma unroll
                for (int j = 0; j < 8; j++) acc[i][j] = fmaf(a[i], bfr[j], acc[i][j]);
        }
    }
#pragma unroll
    for (int i = 0; i < 8; i++) {
        int rg = bm*128 + ty*8 + i;
#pragma unroll
        for (int j = 0; j < 8; j++) {
            int cg = bn*128 + tx*8 + j;
            float v = acc[i][j] + bias[cg];
            if (mode == 1)      v = v / (1.f + __expf(-v));
            else if (mode == 2) v = res[(size_t)rg*DIM + cg] + v;
            C[(size_t)rg*DIM + cg] = v;
        }
    }
}

// ------------------------------ pooling ---------------------------------------
__global__ void score_kernel(const float* __restrict__ p, int dep, int rows) {
    int warp = (blockIdx.x*blockDim.x + threadIdx.x) >> 5;
    int lane = threadIdx.x & 31;
    if (warp >= rows) return;
    const float* hr = g_h + (size_t)warp*DIM;
    float s = 0.f;
#pragma unroll
    for (int q = 0; q < 8; q++) s += hr[lane + 32*q]*p[lane + 32*q];
#pragma unroll
    for (int o = 16; o; o >>= 1) s += __shfl_xor_sync(0xffffffffu, s, o);
    if (lane == 0) g_score[warp] = s * g_pnorm[dep];
}

// exact top-k (matching lax.top_k tie-break) + ascending compaction. one block per batch.
__global__ void topk_kernel(int n, int k) {
    __shared__ float s[NODES];
    __shared__ unsigned char sel[NODES];
    int b = blockIdx.x, t = threadIdx.x, bd = blockDim.x;
    const float* sb = g_score + b*n;
    for (int i = t; i < n; i += bd) s[i] = sb[i];
    __syncthreads();
    for (int i = t; i < n; i += bd) {
        float si = s[i]; int r = 0;
        for (int j = 0; j < n; j++) {
            float sj = s[j];
            r += (sj > si) || (sj == si && j < i);
        }
        sel[i] = (r < k) ? 1 : 0;
    }
    __syncthreads();
    for (int i = t; i < n; i += bd) {
        if (sel[i]) {
            int p = 0;
            for (int j = 0; j < i; j++) p += sel[j];
            g_idx [b*POOLMAX + p] = i;
            g_gate[b*POOLMAX + p] = tanhf(s[i]);
            g_map [b*NODES + i]   = p;
        } else {
            g_map[b*NODES + i] = -1;
        }
    }
}

__global__ void gather_kernel(int n, int k) {
    int b = blockIdx.x / k, r = blockIdx.x % k, d = threadIdx.x;
    int i  = g_idx [b*POOLMAX + r];
    float g = g_gate[b*POOLMAX + r];
    g_t[((size_t)b*k + r)*DIM + d] = g_h[((size_t)b*n + i)*DIM + d] * g;
}

__global__ void copyback_kernel() {
    size_t i = (size_t)blockIdx.x*256 + threadIdx.x;
    g_h[i] = g_t[i];
}

__global__ void subadj_kernel(int n, int k, int oldSel, int newSel) {
    int tid = blockIdx.x*blockDim.x + threadIdx.x;
    if (tid >= BATCH*k) return;
    int b = tid / k, r = tid % k;
    int i = g_idx[b*POOLMAX + r];
    const int* ocols; const int* ocnt; int obase;
    if (oldSel == 0)      { ocols = g_cols0; ocnt = g_cnt0; obase = i; }
    else if (oldSel == 1) { ocols = g_colsA; ocnt = g_cntA; obase = b*POOLMAX + i; }
    else                  { ocols = g_colsB; ocnt = g_cntB; obase = b*POOLMAX + i; }
    int* ncols = (newSel == 1) ? g_colsA : g_colsB;
    int* ncnt  = (newSel == 1) ? g_cntA  : g_cntB;
    int c = ocnt[obase], w = 0, nb = b*POOLMAX + r;
    for (int q = 0; q < c; q++) {
        int j  = ocols[obase*MAXDEG + q];
        int nj = g_map[b*NODES + j];
        if (nj >= 0) ncols[nb*MAXDEG + w++] = nj;
    }
    ncnt[nb] = w;
}

// ------------------------------ readout ---------------------------------------
__global__ void meanstd_kernel(int n) {
    int b = blockIdx.x, d = threadIdx.x;
    const float* hb = g_h + (size_t)b*n*DIM;
    float s = 0.f;
    for (int r = 0; r < n; r++) s += hb[(size_t)r*DIM + d];
    float m = s / (float)n;
    float vs = 0.f;
    for (int r = 0; r < n; r++) { float dd = hb[(size_t)r*DIM + d] - m; vs += dd*dd; }
    float hs = sqrtf(vs / (float)(n - 1)) + 1e-6f;
    g_ms[b*2*DIM + d]       = m;
    g_ms[b*2*DIM + DIM + d] = hs;
}

__global__ void final_kernel(const float* __restrict__ lw, const float* __restrict__ lb,
                             float* __restrict__ out) {
    int b = blockIdx.x, l = threadIdx.x;  // 128 threads
    float acc = lb[l];
    const float* ms = g_ms + b*2*DIM;
    for (int d = 0; d < 2*DIM; d++) acc = fmaf(ms[d], lw[d*128 + l], acc);
    out[b*128 + l] = acc;
}

// ------------------------------ launch ----------------------------------------
extern "C" void kernel_launch(void* const* d_in, const int* in_sizes, int n_in,
                              void* d_out, int out_size) {
    const float* x    = (const float*)d_in[0];
    const float* adj  = (const float*)d_in[1];
    const float* pos  = (const float*)d_in[2];
    const float* in_w = (const float*)d_in[3];
    const float* in_b = (const float*)d_in[4];
    const float* pw1  = (const float*)d_in[5];
    const float* pb1  = (const float*)d_in[6];
    const float* pw2  = (const float*)d_in[7];
    const float* pb2  = (const float*)d_in[8];
    const float* bg   = (const float*)d_in[9];
    const float* bb   = (const float*)d_in[10];
    const float* bw1  = (const float*)d_in[11];
    const float* bb1  = (const float*)d_in[12];
    const float* bw2  = (const float*)d_in[13];
    const float* bb2  = (const float*)d_in[14];
    const float* beps = (const float*)d_in[15];
    const float* pp   = (const float*)d_in[16];
    const float* lw   = (const float*)d_in[17];
    const float* lb   = (const float*)d_in[18];

    float *p_h, *p_hn, *p_t, *p_pe;
    cudaGetSymbolAddress((void**)&p_h,  g_h);
    cudaGetSymbolAddress((void**)&p_hn, g_hn);
    cudaGetSymbolAddress((void**)&p_t,  g_t);
    cudaGetSymbolAddress((void**)&p_pe, g_pe);

    // --- input embedding + positional MLP ---
    pos_stats_kernel<<<1, 256>>>(pos);
    pool_norms_kernel<<<1, 256>>>(pp);
    pos_mid_kernel<<<NODES, 256>>>(pos, pw1, pb1);                       // -> g_hn
    sgemm_kernel<<<dim3(2, NODES/128), 256>>>(p_hn, pw2, pb2, nullptr, p_pe, NODES, 0);
    embed_kernel<<<BATCH*NODES, 256>>>(x, in_w, in_b);                   // -> g_h
    build_csr_kernel<<<NODES/8, 256>>>(adj);

    int n = NODES, adjSel = 0;
    for (int blk = 0; blk < 8; blk++) {
        int rows = BATCH*n;
        ln_kernel<<<rows/8, 256>>>(p_h, p_hn, bg + blk*DIM, bb + blk*DIM, rows);
        combine_kernel<<<rows, 256>>>(n, adjSel, beps, blk);             // g_hn -> g_t
        sgemm_kernel<<<dim3(2, rows/128), 256>>>(p_t, bw1 + blk*DIM*DIM,
                                                 bb1 + blk*DIM, nullptr, p_hn, rows, 1);
        sgemm_kernel<<<dim3(2, rows/128), 256>>>(p_hn, bw2 + blk*DIM*DIM,
                                                 bb2 + blk*DIM, p_h, p_h, rows, 2);
        if ((blk & 1) && blk < 6) {
            int dep = blk >> 1;
            int k = n / 2;
            score_kernel<<<rows/8, 256>>>(pp + dep*DIM, dep, rows);
            topk_kernel<<<BATCH, 1024>>>(n, k);
            gather_kernel<<<BATCH*k, 256>>>(n, k);
            copyback_kernel<<<BATCH*k, 256>>>();
            int newSel = (adjSel == 1) ? 2 : 1;
            subadj_kernel<<<(BATCH*k + 127)/128, 128>>>(n, k, adjSel, newSel);
            adjSel = newSel;
            n = k;
        }
    }

    meanstd_kernel<<<BATCH, 256>>>(n);
    final_kernel<<<BATCH, 128>>>(lw, lb, (float*)d_out);
}

// round 2
// speedup vs baseline: 1.1766x; 1.1766x over previous
#include <cuda_runtime.h>
#include <math.h>

// Problem constants (fixed by setup_inputs)
#define DIM     256
#define BATCH   4
#define NODES   2048
#define MAXDEG  64
#define POOLMAX 1024   // max pooled n (after first pool)

// ---------------- persistent device scratch (no allocs allowed) --------------
__device__ float g_h [BATCH*NODES*DIM];
__device__ float g_h2[BATCH*NODES*DIM];
__device__ float g_hn[BATCH*NODES*DIM];
__device__ float g_t [BATCH*NODES*DIM];
__device__ float g_pe[NODES*DIM];
__device__ float g_score[BATCH*NODES];
__device__ float g_gate [BATCH*POOLMAX];
__device__ float g_ms[BATCH*2*DIM];
__device__ float g_posstat[8];   // mean[3], invstd[3]
__device__ float g_pnorm[4];     // 1/||pool_p[dep]||
__device__ int   g_idx[BATCH*POOLMAX];
__device__ int   g_map[BATCH*NODES];
__device__ int   g_cols0[NODES*MAXDEG];
__device__ int   g_cnt0 [NODES];
__device__ int   g_colsA[BATCH*POOLMAX*MAXDEG];
__device__ int   g_cntA [BATCH*POOLMAX];
__device__ int   g_colsB[BATCH*POOLMAX*MAXDEG];
__device__ int   g_cntB [BATCH*POOLMAX];

// ---------------- f32x2 packed-FMA helpers (sm_10x) ---------------------------
__device__ __forceinline__ unsigned long long pack2s(float x) {
    unsigned long long r;
    asm("mov.b64 %0, {%1, %1};" : "=l"(r) : "f"(x));
    return r;
}
__device__ __forceinline__ unsigned long long pack2(float x, float y) {
    unsigned long long r;
    asm("mov.b64 %0, {%1, %2};" : "=l"(r) : "f"(x), "f"(y));
    return r;
}
__device__ __forceinline__ void ffma2(unsigned long long &d, unsigned long long a,
                                      unsigned long long b) {
    asm("fma.rn.f32x2 %0, %1, %2, %3;" : "=l"(d) : "l"(a), "l"(b), "l"(d));
}
__device__ __forceinline__ void unpack2(unsigned long long v, float &lo, float &hi) {
    asm("mov.b64 {%0, %1}, %2;" : "=f"(lo), "=f"(hi) : "l"(v));
}

// ---------------------------- small utility kernels --------------------------

__global__ void pos_stats_kernel(const float* __restrict__ pos) {
    __shared__ float red[256];
    __shared__ float smean;
    int t = threadIdx.x;
    for (int c = 0; c < 3; c++) {
        float s = 0.f;
        for (int i = t; i < NODES; i += 256) s += pos[i*3 + c];
        red[t] = s; __syncthreads();
        for (int o = 128; o > 0; o >>= 1) { if (t < o) red[t] += red[t+o]; __syncthreads(); }
        if (t == 0) smean = red[0] / (float)NODES;
        __syncthreads();
        float m = smean;
        float ss = 0.f;
        for (int i = t; i < NODES; i += 256) { float d = pos[i*3 + c] - m; ss += d*d; }
        red[t] = ss; __syncthreads();
        for (int o = 128; o > 0; o >>= 1) { if (t < o) red[t] += red[t+o]; __syncthreads(); }
        if (t == 0) {
            float var = (float)BATCH * red[0] / (float)(BATCH*NODES - 1);
            g_posstat[c]   = m;
            g_posstat[3+c] = 1.f / (sqrtf(var) + 1e-8f);
        }
        __syncthreads();
    }
}

__global__ void pool_norms_kernel(const float* __restrict__ pp) {
    __shared__ float red[256];
    int t = threadIdx.x;
    for (int dep = 0; dep < 3; dep++) {
        float v = pp[dep*DIM + t];
        red[t] = v*v; __syncthreads();
        for (int o = 128; o > 0; o >>= 1) { if (t < o) red[t] += red[t+o]; __syncthreads(); }
        if (t == 0) g_pnorm[dep] = 1.f / sqrtf(red[0]);
        __syncthreads();
    }
}

__global__ void pos_mid_kernel(const float* __restrict__ pos,
                               const float* __restrict__ pw1,
                               const float* __restrict__ pb1) {
    int i = blockIdx.x, d = threadIdx.x;
    __shared__ float pn[3];
    if (d < 3) pn[d] = (pos[i*3 + d] - g_posstat[d]) * g_posstat[3+d];
    __syncthreads();
    float a = pb1[d] + pn[0]*pw1[d] + pn[1]*pw1[DIM + d] + pn[2]*pw1[2*DIM + d];
    g_hn[i*DIM + d] = a / (1.f + __expf(-a));
}

__global__ void embed_kernel(const float* __restrict__ x,
                             const float* __restrict__ in_w,
                             const float* __restrict__ in_b) {
    int r = blockIdx.x, d = threadIdx.x;
    __shared__ float xr[16];
    if (d < 16) xr[d] = x[r*16 + d];
    __syncthreads();
    float a = in_b[d] + g_pe[(r & (NODES-1))*DIM + d];
#pragma unroll
    for (int k = 0; k < 16; k++) a += xr[k]*in_w[k*DIM + d];
    g_h[(size_t)r*DIM + d] = a;
}

__global__ void build_csr_kernel(const float* __restrict__ adj) {
    int warp = (blockIdx.x*blockDim.x + threadIdx.x) >> 5;
    int lane = threadIdx.x & 31;
    if (warp >= NODES) return;
    int base = 0;
    for (int it = 0; it < NODES/32; it++) {
        int col = it*32 + lane;
        float v = adj[(size_t)warp*NODES + col];
        unsigned m = __ballot_sync(0xffffffffu, v > 0.f);
        if (v > 0.f) {
            int p = base + __popc(m & ((1u << lane) - 1u));
            if (p < MAXDEG) g_cols0[warp*MAXDEG + p] = col;
        }
        base += __popc(m);
    }
    if (lane == 0) g_cnt0[warp] = base < MAXDEG ? base : MAXDEG;
}

__global__ void ln_kernel(const float* __restrict__ H, float* __restrict__ HN,
                          const float* __restrict__ gam, const float* __restrict__ bet,
                          int rows) {
    int warp = (blockIdx.x*blockDim.x + threadIdx.x) >> 5;
    int lane = threadIdx.x & 31;
    if (warp >= rows) return;
    const float* hr = H + (size_t)warp*DIM;
    float v[8]; float s = 0.f;
#pragma unroll
    for (int q = 0; q < 8; q++) { v[q] = hr[lane + 32*q]; s += v[q]; }
#pragma unroll
    for (int o = 16; o; o >>= 1) s += __shfl_xor_sync(0xffffffffu, s, o);
    float m = s * (1.f/DIM);
    float vs = 0.f;
#pragma unroll
    for (int q = 0; q < 8; q++) { float d = v[q] - m; vs += d*d; }
#pragma unroll
    for (int o = 16; o; o >>= 1) vs += __shfl_xor_sync(0xffffffffu, vs, o);
    float rstd = rsqrtf(vs * (1.f/DIM) + 1e-5f);
#pragma unroll
    for (int q = 0; q < 8; q++) {
        int d = lane + 32*q;
        HN[(size_t)warp*DIM + d] = (v[q] - m)*rstd*gam[d] + bet[d];
    }
}

__global__ void combine_kernel(int n, int adjSel, const float* __restrict__ beps, int blk) {
    int b = blockIdx.x / n, i = blockIdx.x % n, d = threadIdx.x;
    const int* cols; const int* cnt; int rowbase;
    if (adjSel == 0)      { cols = g_cols0; cnt = g_cnt0; rowbase = i; }
    else if (adjSel == 1) { cols = g_colsA; cnt = g_cntA; rowbase = b*POOLMAX + i; }
    else                  { cols = g_colsB; cnt = g_cntB; rowbase = b*POOLMAX + i; }
    __shared__ int cs[MAXDEG];
    int c = cnt[rowbase];
    if (d < c) cs[d] = cols[rowbase*MAXDEG + d];
    __syncthreads();
    float eps = beps[blk];
    const float* hb = g_hn + (size_t)b*n*DIM;
    float acc = (1.f + eps)*hb[(size_t)i*DIM + d];
    for (int q = 0; q < c; q++) acc += hb[(size_t)cs[q]*DIM + d];
    g_t[((size_t)b*n + i)*DIM + d] = acc;
}

// ------------------- SGEMM (M x 256 x 256), f32x2, double-buffered ------------
// 128x128 tile, BK=8, 256 threads, per-thread 8m x 8n = 8 x 4 f32x2.
// mode 0: C = acc+bias ; 1: C = silu(acc+bias) ; 2: C = res + acc + bias
__global__ __launch_bounds__(256, 2)
void sgemm_kernel(const float* __restrict__ A, const float* __restrict__ Bw,
                  const float* __restrict__ bias, const float* __restrict__ res,
                  float* __restrict__ C, int M, int mode) {
    __shared__ float As[2][8][128];
    __shared__ float Bs[2][8][128];
    int t  = threadIdx.x;
    int bm = blockIdx.y, bn = blockIdx.x;
    int ty = t >> 4, tx = t & 15;
    int arow = t >> 1, acol = (t & 1)*4;
    int brow = t >> 5, bcol = (t & 31)*4;
    const float* Ap = A  + (size_t)(bm*128 + arow)*DIM + acol;
    const float* Bp = Bw + (size_t)brow*DIM + bn*128 + bcol;

    unsigned long long acc[8][4];
#pragma unroll
    for (int i = 0; i < 8; i++)
#pragma unroll
        for (int j = 0; j < 4; j++) acc[i][j] = 0ull;

    // preload k0 = 0
    float4 av = *(const float4*)(Ap);
    float4 bv = *(const float4*)(Bp);
    As[0][acol+0][arow] = av.x; As[0][acol+1][arow] = av.y;
    As[0][acol+2][arow] = av.z; As[0][acol+3][arow] = av.w;
    *(float4*)&Bs[0][brow][bcol] = bv;
    __syncthreads();

    int cur = 0;
#pragma unroll 4
    for (int k0 = 8; k0 < DIM; k0 += 8) {
        // prefetch next tile (global)
        av = *(const float4*)(Ap + k0);
        bv = *(const float4*)(Bp + (size_t)k0*DIM);
        // compute current
#pragma unroll
        for (int kk = 0; kk < 8; kk++) {
            float4 aA = *(const float4*)&As[cur][kk][ty*8];
            float4 aB = *(const float4*)&As[cur][kk][ty*8 + 4];
            float4 bA = *(const float4*)&Bs[cur][kk][tx*8];
            float4 bB = *(const float4*)&Bs[cur][kk][tx*8 + 4];
            unsigned long long bp[4] = { pack2(bA.x, bA.y), pack2(bA.z, bA.w),
                                         pack2(bB.x, bB.y), pack2(bB.z, bB.w) };
            float am[8] = { aA.x, aA.y, aA.z, aA.w, aB.x, aB.y, aB.z, aB.w };
#pragma unroll
            for (int i = 0; i < 8; i++) {
                unsigned long long ap = pack2s(am[i]);
#pragma unroll
                for (int j = 0; j < 4; j++) ffma2(acc[i][j], ap, bp[j]);
            }
        }
        int nxt = cur ^ 1;
        As[nxt][acol+0][arow] = av.x; As[nxt][acol+1][arow] = av.y;
        As[nxt][acol+2][arow] = av.z; As[nxt][acol+3][arow] = av.w;
        *(float4*)&Bs[nxt][brow][bcol] = bv;
        __syncthreads();
        cur = nxt;
    }
    // last tile
#pragma unroll
    for (int kk = 0; kk < 8; kk++) {
        float4 aA = *(const float4*)&As[cur][kk][ty*8];
        float4 aB = *(const float4*)&As[cur][kk][ty*8 + 4];
        float4 bA = *(const float4*)&Bs[cur][kk][tx*8];
        float4 bB = *(const float4*)&Bs[cur][kk][tx*8 + 4];
        unsigned long long bp[4] = { pack2(bA.x, bA.y), pack2(bA.z, bA.w),
                                     pack2(bB.x, bB.y), pack2(bB.z, bB.w) };
        float am[8] = { aA.x, aA.y, aA.z, aA.w, aB.x, aB.y, aB.z, aB.w };
#pragma unroll
        for (int i = 0; i < 8; i++) {
            unsigned long long ap = pack2s(am[i]);
#pragma unroll
            for (int j = 0; j < 4; j++) ffma2(acc[i][j], ap, bp[j]);
        }
    }

#pragma unroll
    for (int i = 0; i < 8; i++) {
        int rg = bm*128 + ty*8 + i;
#pragma unroll
        for (int j = 0; j < 4; j++) {
            int cg = bn*128 + tx*8 + j*2;
            float lo, hi;
            unpack2(acc[i][j], lo, hi);
            float v0 = lo + bias[cg];
            float v1 = hi + bias[cg + 1];
            if (mode == 1) {
                v0 = v0 / (1.f + __expf(-v0));
                v1 = v1 / (1.f + __expf(-v1));
            } else if (mode == 2) {
                v0 = res[(size_t)rg*DIM + cg]     + v0;
                v1 = res[(size_t)rg*DIM + cg + 1] + v1;
            }
            C[(size_t)rg*DIM + cg]     = v0;
            C[(size_t)rg*DIM + cg + 1] = v1;
        }
    }
}

// ------------------------------ pooling ---------------------------------------
__global__ void score_kernel(const float* __restrict__ H, const float* __restrict__ p,
                             int dep, int rows) {
    int warp = (blockIdx.x*blockDim.x + threadIdx.x) >> 5;
    int lane = threadIdx.x & 31;
    if (warp >= rows) return;
    const float* hr = H + (size_t)warp*DIM;
    float s = 0.f;
#pragma unroll
    for (int q = 0; q < 8; q++) s += hr[lane + 32*q]*p[lane + 32*q];
#pragma unroll
    for (int o = 16; o; o >>= 1) s += __shfl_xor_sync(0xffffffffu, s, o);
    if (lane == 0) g_score[warp] = s * g_pnorm[dep];
}

__global__ void topk_kernel(int n, int k) {
    __shared__ float s[NODES];
    __shared__ unsigned char sel[NODES];
    int b = blockIdx.x, t = threadIdx.x, bd = blockDim.x;
    const float* sb = g_score + b*n;
    for (int i = t; i < n; i += bd) s[i] = sb[i];
    __syncthreads();
    for (int i = t; i < n; i += bd) {
        float si = s[i]; int r = 0;
        for (int j = 0; j < n; j++) {
            float sj = s[j];
            r += (sj > si) || (sj == si && j < i);
        }
        sel[i] = (r < k) ? 1 : 0;
    }
    __syncthreads();
    for (int i = t; i < n; i += bd) {
        if (sel[i]) {
            int p = 0;
            for (int j = 0; j < i; j++) p += sel[j];
            g_idx [b*POOLMAX + p] = i;
            g_gate[b*POOLMAX + p] = tanhf(s[i]);
            g_map [b*NODES + i]   = p;
        } else {
            g_map[b*NODES + i] = -1;
        }
    }
}

__global__ void gather_kernel(const float* __restrict__ H, float* __restrict__ O,
                              int n, int k) {
    int b = blockIdx.x / k, r = blockIdx.x % k, d = threadIdx.x;
    int i  = g_idx [b*POOLMAX + r];
    float g = g_gate[b*POOLMAX + r];
    O[((size_t)b*k + r)*DIM + d] = H[((size_t)b*n + i)*DIM + d] * g;
}

__global__ void subadj_kernel(int n, int k, int oldSel, int newSel) {
    int tid = blockIdx.x*blockDim.x + threadIdx.x;
    if (tid >= BATCH*k) return;
    int b = tid / k, r = tid % k;
    int i = g_idx[b*POOLMAX + r];
    const int* ocols; const int* ocnt; int obase;
    if (oldSel == 0)      { ocols = g_cols0; ocnt = g_cnt0; obase = i; }
    else if (oldSel == 1) { ocols = g_colsA; ocnt = g_cntA; obase = b*POOLMAX + i; }
    else                  { ocols = g_colsB; ocnt = g_cntB; obase = b*POOLMAX + i; }
    int* ncols = (newSel == 1) ? g_colsA : g_colsB;
    int* ncnt  = (newSel == 1) ? g_cntA  : g_cntB;
    int c = ocnt[obase], w = 0, nb = b*POOLMAX + r;
    for (int q = 0; q < c; q++) {
        int j  = ocols[obase*MAXDEG + q];
        int nj = g_map[b*NODES + j];
        if (nj >= 0) ncols[nb*MAXDEG + w++] = nj;
    }
    ncnt[nb] = w;
}

// ------------------------------ readout ---------------------------------------
__global__ void meanstd_kernel(const float* __restrict__ H, int n) {
    int b = blockIdx.x, d = threadIdx.x;
    const float* hb = H + (size_t)b*n*DIM;
    float s = 0.f;
    for (int r = 0; r < n; r++) s += hb[(size_t)r*DIM + d];
    float m = s / (float)n;
    float vs = 0.f;
    for (int r = 0; r < n; r++) { float dd = hb[(size_t)r*DIM + d] - m; vs += dd*dd; }
    float hs = sqrtf(vs / (float)(n - 1)) + 1e-6f;
    g_ms[b*2*DIM + d]       = m;
    g_ms[b*2*DIM + DIM + d] = hs;
}

__global__ void final_kernel(const float* __restrict__ lw, const float* __restrict__ lb,
                             float* __restrict__ out) {
    int b = blockIdx.x, l = threadIdx.x;  // 128 threads
    float acc = lb[l];
    const float* ms = g_ms + b*2*DIM;
    for (int d = 0; d < 2*DIM; d++) acc = fmaf(ms[d], lw[d*128 + l], acc);
    out[b*128 + l] = acc;
}

// ------------------------------ launch ----------------------------------------
extern "C" void kernel_launch(void* const* d_in, const int* in_sizes, int n_in,
                              void* d_out, int out_size) {
    const float* x    = (const float*)d_in[0];
    const float* adj  = (const float*)d_in[1];
    const float* pos  = (const float*)d_in[2];
    const float* in_w = (const float*)d_in[3];
    const float* in_b = (const float*)d_in[4];
    const float* pw1  = (const float*)d_in[5];
    const float* pb1  = (const float*)d_in[6];
    const float* pw2  = (const float*)d_in[7];
    const float* pb2  = (const float*)d_in[8];
    const float* bg   = (const float*)d_in[9];
    const float* bb   = (const float*)d_in[10];
    const float* bw1  = (const float*)d_in[11];
    const float* bb1  = (const float*)d_in[12];
    const float* bw2  = (const float*)d_in[13];
    const float* bb2  = (const float*)d_in[14];
    const float* beps = (const float*)d_in[15];
    const float* pp   = (const float*)d_in[16];
    const float* lw   = (const float*)d_in[17];
    const float* lb   = (const float*)d_in[18];

    float *p_h, *p_h2, *p_hn, *p_t, *p_pe;
    cudaGetSymbolAddress((void**)&p_h,  g_h);
    cudaGetSymbolAddress((void**)&p_h2, g_h2);
    cudaGetSymbolAddress((void**)&p_hn, g_hn);
    cudaGetSymbolAddress((void**)&p_t,  g_t);
    cudaGetSymbolAddress((void**)&p_pe, g_pe);

    // --- input embedding + positional MLP ---
    pos_stats_kernel<<<1, 256>>>(pos);
    pool_norms_kernel<<<1, 256>>>(pp);
    pos_mid_kernel<<<NODES, 256>>>(pos, pw1, pb1);                       // -> g_hn
    sgemm_kernel<<<dim3(2, NODES/128), 256>>>(p_hn, pw2, pb2, nullptr, p_pe, NODES, 0);
    embed_kernel<<<BATCH*NODES, 256>>>(x, in_w, in_b);                   // -> g_h
    build_csr_kernel<<<NODES/8, 256>>>(adj);

    float* curH = p_h;
    int n = NODES, adjSel = 0;
    for (int blk = 0; blk < 8; blk++) {
        int rows = BATCH*n;
        ln_kernel<<<rows/8, 256>>>(curH, p_hn, bg + blk*DIM, bb + blk*DIM, rows);
        combine_kernel<<<rows, 256>>>(n, adjSel, beps, blk);             // g_hn -> g_t
        sgemm_kernel<<<dim3(2, rows/128), 256>>>(p_t, bw1 + blk*DIM*DIM,
                                                 bb1 + blk*DIM, nullptr, p_hn, rows, 1);
        sgemm_kernel<<<dim3(2, rows/128), 256>>>(p_hn, bw2 + blk*DIM*DIM,
                                                 bb2 + blk*DIM, curH, curH, rows, 2);
        if ((blk & 1) && blk < 6) {
            int dep = blk >> 1;
            int k = n / 2;
            score_kernel<<<rows/8, 256>>>(curH, pp + dep*DIM, dep, rows);
            topk_kernel<<<BATCH, 1024>>>(n, k);
            float* newH = (curH == p_h) ? p_h2 : p_h;
            gather_kernel<<<BATCH*k, 256>>>(curH, newH, n, k);
            int newSel = (adjSel == 1) ? 2 : 1;
            subadj_kernel<<<(BATCH*k + 127)/128, 128>>>(n, k, adjSel, newSel);
            adjSel = newSel;
            curH = newH;
            n = k;
        }
    }

    meanstd_kernel<<<BATCH, 256>>>(curH, n);
    final_kernel<<<BATCH, 128>>>(lw, lb, (float*)d_out);
}

// round 3
// speedup vs baseline: 1.3664x; 1.1613x over previous
#include <cuda_runtime.h>
#include <math.h>

// Problem constants (fixed by setup_inputs)
#define DIM     256
#define BATCH   4
#define NODES   2048
#define MAXDEG  64
#define POOLMAX 1024   // max pooled n (after first pool)

// ---------------- persistent device scratch (no allocs allowed) --------------
__device__ float g_h [BATCH*NODES*DIM];
__device__ float g_h2[BATCH*NODES*DIM];
__device__ float g_hn[BATCH*NODES*DIM];
__device__ float g_t [BATCH*NODES*DIM];
__device__ float g_pe[NODES*DIM];
__device__ float g_score[BATCH*NODES];
__device__ float g_gate [BATCH*POOLMAX];
__device__ float g_ms[BATCH*2*DIM];
__device__ float g_posstat[8];   // mean[3], invstd[3]
__device__ float g_pnorm[4];     // 1/||pool_p[dep]||
__device__ int   g_idx[BATCH*POOLMAX];
__device__ int   g_map[BATCH*NODES];
__device__ int   g_cols0[NODES*MAXDEG];
__device__ int   g_cnt0 [NODES];
__device__ int   g_colsA[BATCH*POOLMAX*MAXDEG];
__device__ int   g_cntA [BATCH*POOLMAX];
__device__ int   g_colsB[BATCH*POOLMAX*MAXDEG];
__device__ int   g_cntB [BATCH*POOLMAX];

// ---------------- f32x2 packed-FMA helpers (sm_10x) ---------------------------
__device__ __forceinline__ unsigned long long pack2s(float x) {
    unsigned long long r;
    asm("mov.b64 %0, {%1, %1};" : "=l"(r) : "f"(x));
    return r;
}
__device__ __forceinline__ unsigned long long pack2(float x, float y) {
    unsigned long long r;
    asm("mov.b64 %0, {%1, %2};" : "=l"(r) : "f"(x), "f"(y));
    return r;
}
__device__ __forceinline__ void ffma2(unsigned long long &d, unsigned long long a,
                                      unsigned long long b) {
    asm("fma.rn.f32x2 %0, %1, %2, %3;" : "=l"(d) : "l"(a), "l"(b), "l"(d));
}
__device__ __forceinline__ void unpack2(unsigned long long v, float &lo, float &hi) {
    asm("mov.b64 {%0, %1}, %2;" : "=f"(lo), "=f"(hi) : "l"(v));
}

// ---------------------------- small utility kernels --------------------------

__global__ void pos_stats_kernel(const float* __restrict__ pos) {
    __shared__ float red[256];
    __shared__ float smean;
    int t = threadIdx.x;
    for (int c = 0; c < 3; c++) {
        float s = 0.f;
        for (int i = t; i < NODES; i += 256) s += pos[i*3 + c];
        red[t] = s; __syncthreads();
        for (int o = 128; o > 0; o >>= 1) { if (t < o) red[t] += red[t+o]; __syncthreads(); }
        if (t == 0) smean = red[0] / (float)NODES;
        __syncthreads();
        float m = smean;
        float ss = 0.f;
        for (int i = t; i < NODES; i += 256) { float d = pos[i*3 + c] - m; ss += d*d; }
        red[t] = ss; __syncthreads();
        for (int o = 128; o > 0; o >>= 1) { if (t < o) red[t] += red[t+o]; __syncthreads(); }
        if (t == 0) {
            float var = (float)BATCH * red[0] / (float)(BATCH*NODES - 1);
            g_posstat[c]   = m;
            g_posstat[3+c] = 1.f / (sqrtf(var) + 1e-8f);
        }
        __syncthreads();
    }
}

__global__ void pool_norms_kernel(const float* __restrict__ pp) {
    __shared__ float red[256];
    int t = threadIdx.x;
    for (int dep = 0; dep < 3; dep++) {
        float v = pp[dep*DIM + t];
        red[t] = v*v; __syncthreads();
        for (int o = 128; o > 0; o >>= 1) { if (t < o) red[t] += red[t+o]; __syncthreads(); }
        if (t == 0) g_pnorm[dep] = 1.f / sqrtf(red[0]);
        __syncthreads();
    }
}

__global__ void pos_mid_kernel(const float* __restrict__ pos,
                               const float* __restrict__ pw1,
                               const float* __restrict__ pb1) {
    int i = blockIdx.x, d = threadIdx.x;
    __shared__ float pn[3];
    if (d < 3) pn[d] = (pos[i*3 + d] - g_posstat[d]) * g_posstat[3+d];
    __syncthreads();
    float a = pb1[d] + pn[0]*pw1[d] + pn[1]*pw1[DIM + d] + pn[2]*pw1[2*DIM + d];
    g_hn[i*DIM + d] = a / (1.f + __expf(-a));
}

__global__ void embed_kernel(const float* __restrict__ x,
                             const float* __restrict__ in_w,
                             const float* __restrict__ in_b) {
    int r = blockIdx.x, d = threadIdx.x;
    __shared__ float xr[16];
    if (d < 16) xr[d] = x[r*16 + d];
    __syncthreads();
    float a = in_b[d] + g_pe[(r & (NODES-1))*DIM + d];
#pragma unroll
    for (int k = 0; k < 16; k++) a += xr[k]*in_w[k*DIM + d];
    g_h[(size_t)r*DIM + d] = a;
}

__global__ void build_csr_kernel(const float* __restrict__ adj) {
    int warp = (blockIdx.x*blockDim.x + threadIdx.x) >> 5;
    int lane = threadIdx.x & 31;
    if (warp >= NODES) return;
    int base = 0;
    for (int it = 0; it < NODES/32; it++) {
        int col = it*32 + lane;
        float v = adj[(size_t)warp*NODES + col];
        unsigned m = __ballot_sync(0xffffffffu, v > 0.f);
        if (v > 0.f) {
            int p = base + __popc(m & ((1u << lane) - 1u));
            if (p < MAXDEG) g_cols0[warp*MAXDEG + p] = col;
        }
        base += __popc(m);
    }
    if (lane == 0) g_cnt0[warp] = base < MAXDEG ? base : MAXDEG;
}

__global__ void ln_kernel(const float* __restrict__ H, float* __restrict__ HN,
                          const float* __restrict__ gam, const float* __restrict__ bet,
                          int rows) {
    int warp = (blockIdx.x*blockDim.x + threadIdx.x) >> 5;
    int lane = threadIdx.x & 31;
    if (warp >= rows) return;
    const float* hr = H + (size_t)warp*DIM;
    float v[8]; float s = 0.f;
#pragma unroll
    for (int q = 0; q < 8; q++) { v[q] = hr[lane + 32*q]; s += v[q]; }
#pragma unroll
    for (int o = 16; o; o >>= 1) s += __shfl_xor_sync(0xffffffffu, s, o);
    float m = s * (1.f/DIM);
    float vs = 0.f;
#pragma unroll
    for (int q = 0; q < 8; q++) { float d = v[q] - m; vs += d*d; }
#pragma unroll
    for (int o = 16; o; o >>= 1) vs += __shfl_xor_sync(0xffffffffu, vs, o);
    float rstd = rsqrtf(vs * (1.f/DIM) + 1e-5f);
#pragma unroll
    for (int q = 0; q < 8; q++) {
        int d = lane + 32*q;
        HN[(size_t)warp*DIM + d] = (v[q] - m)*rstd*gam[d] + bet[d];
    }
}

__global__ void combine_kernel(int n, int adjSel, const float* __restrict__ beps, int blk) {
    int b = blockIdx.x / n, i = blockIdx.x % n, d = threadIdx.x;
    const int* cols; const int* cnt; int rowbase;
    if (adjSel == 0)      { cols = g_cols0; cnt = g_cnt0; rowbase = i; }
    else if (adjSel == 1) { cols = g_colsA; cnt = g_cntA; rowbase = b*POOLMAX + i; }
    else                  { cols = g_colsB; cnt = g_cntB; rowbase = b*POOLMAX + i; }
    __shared__ int cs[MAXDEG];
    int c = cnt[rowbase];
    if (d < c) cs[d] = cols[rowbase*MAXDEG + d];
    __syncthreads();
    float eps = beps[blk];
    const float* hb = g_hn + (size_t)b*n*DIM;
    float acc = (1.f + eps)*hb[(size_t)i*DIM + d];
    for (int q = 0; q < c; q++) acc += hb[(size_t)cs[q]*DIM + d];
    g_t[((size_t)b*n + i)*DIM + d] = acc;
}

// ------------- SGEMM (M x 256 x 256), f32x2, 64x64 tile, double-buffered ------
// BK=16, 128 threads, per-thread 4m x 8n (4 f32x2 per row).
// mode 0: C = acc+bias ; 1: C = silu(acc+bias) ; 2: C = res + acc + bias
__global__ __launch_bounds__(128, 4)
void sgemm_kernel(const float* __restrict__ A, const float* __restrict__ Bw,
                  const float* __restrict__ bias, const float* __restrict__ res,
                  float* __restrict__ C, int M, int mode) {
    __shared__ float As[2][16][64];
    __shared__ float Bs[2][16][64];
    int t  = threadIdx.x;
    int bm = blockIdx.y, bn = blockIdx.x;
    int ty = t >> 3, tx = t & 7;          // 16 x 8 thread grid
    int arow = t >> 1, acol = (t & 1)*8;  // A: 64 rows x 16 k, 2 float4 each
    int brow = t >> 3, bcol = (t & 7)*8;  // B: 16 rows x 64 n, 2 float4 each
    const float* Ap = A  + (size_t)(bm*64 + arow)*DIM + acol;
    const float* Bp = Bw + (size_t)brow*DIM + bn*64 + bcol;

    unsigned long long acc[4][4];
#pragma unroll
    for (int i = 0; i < 4; i++)
#pragma unroll
        for (int j = 0; j < 4; j++) acc[i][j] = 0ull;

    // preload k0 = 0
    float4 av0 = *(const float4*)(Ap);
    float4 av1 = *(const float4*)(Ap + 4);
    float4 bv0 = *(const float4*)(Bp);
    float4 bv1 = *(const float4*)(Bp + 4);
    As[0][acol+0][arow] = av0.x; As[0][acol+1][arow] = av0.y;
    As[0][acol+2][arow] = av0.z; As[0][acol+3][arow] = av0.w;
    As[0][acol+4][arow] = av1.x; As[0][acol+5][arow] = av1.y;
    As[0][acol+6][arow] = av1.z; As[0][acol+7][arow] = av1.w;
    *(float4*)&Bs[0][brow][bcol]     = bv0;
    *(float4*)&Bs[0][brow][bcol + 4] = bv1;
    __syncthreads();

    int cur = 0;
    for (int k0 = 16; k0 < DIM; k0 += 16) {
        // prefetch next tile (global)
        av0 = *(const float4*)(Ap + k0);
        av1 = *(const float4*)(Ap + k0 + 4);
        bv0 = *(const float4*)(Bp + (size_t)k0*DIM);
        bv1 = *(const float4*)(Bp + (size_t)k0*DIM + 4);
        // compute current
#pragma unroll
        for (int kk = 0; kk < 16; kk++) {
            float4 a4 = *(const float4*)&As[cur][kk][ty*4];
            float4 bA = *(const float4*)&Bs[cur][kk][tx*8];
            float4 bB = *(const float4*)&Bs[cur][kk][tx*8 + 4];
            unsigned long long bp[4] = { pack2(bA.x, bA.y), pack2(bA.z, bA.w),
                                         pack2(bB.x, bB.y), pack2(bB.z, bB.w) };
            float am[4] = { a4.x, a4.y, a4.z, a4.w };
#pragma unroll
            for (int i = 0; i < 4; i++) {
                unsigned long long ap = pack2s(am[i]);
#pragma unroll
                for (int j = 0; j < 4; j++) ffma2(acc[i][j], ap, bp[j]);
            }
        }
        int nxt = cur ^ 1;
        As[nxt][acol+0][arow] = av0.x; As[nxt][acol+1][arow] = av0.y;
        As[nxt][acol+2][arow] = av0.z; As[nxt][acol+3][arow] = av0.w;
        As[nxt][acol+4][arow] = av1.x; As[nxt][acol+5][arow] = av1.y;
        As[nxt][acol+6][arow] = av1.z; As[nxt][acol+7][arow] = av1.w;
        *(float4*)&Bs[nxt][brow][bcol]     = bv0;
        *(float4*)&Bs[nxt][brow][bcol + 4] = bv1;
        __syncthreads();
        cur = nxt;
    }
    // last tile
#pragma unroll
    for (int kk = 0; kk < 16; kk++) {
        float4 a4 = *(const float4*)&As[cur][kk][ty*4];
        float4 bA = *(const float4*)&Bs[cur][kk][tx*8];
        float4 bB = *(const float4*)&Bs[cur][kk][tx*8 + 4];
        unsigned long long bp[4] = { pack2(bA.x, bA.y), pack2(bA.z, bA.w),
                                     pack2(bB.x, bB.y), pack2(bB.z, bB.w) };
        float am[4] = { a4.x, a4.y, a4.z, a4.w };
#pragma unroll
        for (int i = 0; i < 4; i++) {
            unsigned long long ap = pack2s(am[i]);
#pragma unroll
            for (int j = 0; j < 4; j++) ffma2(acc[i][j], ap, bp[j]);
        }
    }

#pragma unroll
    for (int i = 0; i < 4; i++) {
        int rg = bm*64 + ty*4 + i;
#pragma unroll
        for (int j = 0; j < 4; j++) {
            int cg = bn*64 + tx*8 + j*2;
            float lo, hi;
            unpack2(acc[i][j], lo, hi);
            float v0 = lo + bias[cg];
            float v1 = hi + bias[cg + 1];
            if (mode == 1) {
                v0 = v0 / (1.f + __expf(-v0));
                v1 = v1 / (1.f + __expf(-v1));
            } else if (mode == 2) {
                v0 = res[(size_t)rg*DIM + cg]     + v0;
                v1 = res[(size_t)rg*DIM + cg + 1] + v1;
            }
            C[(size_t)rg*DIM + cg]     = v0;
            C[(size_t)rg*DIM + cg + 1] = v1;
        }
    }
}

// ------------------------------ pooling ---------------------------------------
__global__ void score_kernel(const float* __restrict__ H, const float* __restrict__ p,
                             int dep, int rows) {
    int warp = (blockIdx.x*blockDim.x + threadIdx.x) >> 5;
    int lane = threadIdx.x & 31;
    if (warp >= rows) return;
    const float* hr = H + (size_t)warp*DIM;
    float s = 0.f;
#pragma unroll
    for (int q = 0; q < 8; q++) s += hr[lane + 32*q]*p[lane + 32*q];
#pragma unroll
    for (int o = 16; o; o >>= 1) s += __shfl_xor_sync(0xffffffffu, s, o);
    if (lane == 0) g_score[warp] = s * g_pnorm[dep];
}

__global__ void topk_kernel(int n, int k) {
    __shared__ float s[NODES];
    __shared__ unsigned char sel[NODES];
    int b = blockIdx.x, t = threadIdx.x, bd = blockDim.x;
    const float* sb = g_score + b*n;
    for (int i = t; i < n; i += bd) s[i] = sb[i];
    __syncthreads();
    for (int i = t; i < n; i += bd) {
        float si = s[i]; int r = 0;
        for (int j = 0; j < n; j++) {
            float sj = s[j];
            r += (sj > si) || (sj == si && j < i);
        }
        sel[i] = (r < k) ? 1 : 0;
    }
    __syncthreads();
    for (int i = t; i < n; i += bd) {
        if (sel[i]) {
            int p = 0;
            for (int j = 0; j < i; j++) p += sel[j];
            g_idx [b*POOLMAX + p] = i;
            g_gate[b*POOLMAX + p] = tanhf(s[i]);
            g_map [b*NODES + i]   = p;
        } else {
            g_map[b*NODES + i] = -1;
        }
    }
}

__global__ void gather_kernel(const float* __restrict__ H, float* __restrict__ O,
                              int n, int k) {
    int b = blockIdx.x / k, r = blockIdx.x % k, d = threadIdx.x;
    int i  = g_idx [b*POOLMAX + r];
    float g = g_gate[b*POOLMAX + r];
    O[((size_t)b*k + r)*DIM + d] = H[((size_t)b*n + i)*DIM + d] * g;
}

__global__ void subadj_kernel(int n, int k, int oldSel, int newSel) {
    int tid = blockIdx.x*blockDim.x + threadIdx.x;
    if (tid >= BATCH*k) return;
    int b = tid / k, r = tid % k;
    int i = g_idx[b*POOLMAX + r];
    const int* ocols; const int* ocnt; int obase;
    if (oldSel == 0)      { ocols = g_cols0; ocnt = g_cnt0; obase = i; }
    else if (oldSel == 1) { ocols = g_colsA; ocnt = g_cntA; obase = b*POOLMAX + i; }
    else                  { ocols = g_colsB; ocnt = g_cntB; obase = b*POOLMAX + i; }
    int* ncols = (newSel == 1) ? g_colsA : g_colsB;
    int* ncnt  = (newSel == 1) ? g_cntA  : g_cntB;
    int c = ocnt[obase], w = 0, nb = b*POOLMAX + r;
    for (int q = 0; q < c; q++) {
        int j  = ocols[obase*MAXDEG + q];
        int nj = g_map[b*NODES + j];
        if (nj >= 0) ncols[nb*MAXDEG + w++] = nj;
    }
    ncnt[nb] = w;
}

// ------------------------------ readout ---------------------------------------
__global__ void meanstd_kernel(const float* __restrict__ H, int n) {
    int b = blockIdx.x, d = threadIdx.x;
    const float* hb = H + (size_t)b*n*DIM;
    float s = 0.f;
    for (int r = 0; r < n; r++) s += hb[(size_t)r*DIM + d];
    float m = s / (float)n;
    float vs = 0.f;
    for (int r = 0; r < n; r++) { float dd = hb[(size_t)r*DIM + d] - m; vs += dd*dd; }
    float hs = sqrtf(vs / (float)(n - 1)) + 1e-6f;
    g_ms[b*2*DIM + d]       = m;
    g_ms[b*2*DIM + DIM + d] = hs;
}

__global__ void final_kernel(const float* __restrict__ lw, const float* __restrict__ lb,
                             float* __restrict__ out) {
    int b = blockIdx.x, l = threadIdx.x;  // 128 threads
    float acc = lb[l];
    const float* ms = g_ms + b*2*DIM;
    for (int d = 0; d < 2*DIM; d++) acc = fmaf(ms[d], lw[d*128 + l], acc);
    out[b*128 + l] = acc;
}

// ------------------------------ launch ----------------------------------------
extern "C" void kernel_launch(void* const* d_in, const int* in_sizes, int n_in,
                              void* d_out, int out_size) {
    const float* x    = (const float*)d_in[0];
    const float* adj  = (const float*)d_in[1];
    const float* pos  = (const float*)d_in[2];
    const float* in_w = (const float*)d_in[3];
    const float* in_b = (const float*)d_in[4];
    const float* pw1  = (const float*)d_in[5];
    const float* pb1  = (const float*)d_in[6];
    const float* pw2  = (const float*)d_in[7];
    const float* pb2  = (const float*)d_in[8];
    const float* bg   = (const float*)d_in[9];
    const float* bb   = (const float*)d_in[10];
    const float* bw1  = (const float*)d_in[11];
    const float* bb1  = (const float*)d_in[12];
    const float* bw2  = (const float*)d_in[13];
    const float* bb2  = (const float*)d_in[14];
    const float* beps = (const float*)d_in[15];
    const float* pp   = (const float*)d_in[16];
    const float* lw   = (const float*)d_in[17];
    const float* lb   = (const float*)d_in[18];

    float *p_h, *p_h2, *p_hn, *p_t, *p_pe;
    cudaGetSymbolAddress((void**)&p_h,  g_h);
    cudaGetSymbolAddress((void**)&p_h2, g_h2);
    cudaGetSymbolAddress((void**)&p_hn, g_hn);
    cudaGetSymbolAddress((void**)&p_t,  g_t);
    cudaGetSymbolAddress((void**)&p_pe, g_pe);

    // --- input embedding + positional MLP ---
    pos_stats_kernel<<<1, 256>>>(pos);
    pool_norms_kernel<<<1, 256>>>(pp);
    pos_mid_kernel<<<NODES, 256>>>(pos, pw1, pb1);                       // -> g_hn
    sgemm_kernel<<<dim3(4, NODES/64), 128>>>(p_hn, pw2, pb2, nullptr, p_pe, NODES, 0);
    embed_kernel<<<BATCH*NODES, 256>>>(x, in_w, in_b);                   // -> g_h
    build_csr_kernel<<<NODES/8, 256>>>(adj);

    float* curH = p_h;
    int n = NODES, adjSel = 0;
    for (int blk = 0; blk < 8; blk++) {
        int rows = BATCH*n;
        ln_kernel<<<rows/8, 256>>>(curH, p_hn, bg + blk*DIM, bb + blk*DIM, rows);
        combine_kernel<<<rows, 256>>>(n, adjSel, beps, blk);             // g_hn -> g_t
        sgemm_kernel<<<dim3(4, rows/64), 128>>>(p_t, bw1 + blk*DIM*DIM,
                                                bb1 + blk*DIM, nullptr, p_hn, rows, 1);
        sgemm_kernel<<<dim3(4, rows/64), 128>>>(p_hn, bw2 + blk*DIM*DIM,
                                                bb2 + blk*DIM, curH, curH, rows, 2);
        if ((blk & 1) && blk < 6) {
            int dep = blk >> 1;
            int k = n / 2;
            score_kernel<<<rows/8, 256>>>(curH, pp + dep*DIM, dep, rows);
            topk_kernel<<<BATCH, 1024>>>(n, k);
            float* newH = (curH == p_h) ? p_h2 : p_h;
            gather_kernel<<<BATCH*k, 256>>>(curH, newH, n, k);
            int newSel = (adjSel == 1) ? 2 : 1;
            subadj_kernel<<<(BATCH*k + 127)/128, 128>>>(n, k, adjSel, newSel);
            adjSel = newSel;
            curH = newH;
            n = k;
        }
    }

    meanstd_kernel<<<BATCH, 256>>>(curH, n);
    final_kernel<<<BATCH, 128>>>(lw, lb, (float*)d_out);
}